// round 1
// baseline (speedup 1.0000x reference)
#include <cuda_runtime.h>
#include <math.h>

#define Nn 2048
#define Dd 256
#define Hh 8
#define DKk 32
#define Ll 4
#define DFFf 1024
#define NEDGEe 5

// ---------------- scratch (static device globals: no allocation) ----------------
__device__ float g_x[Nn * Dd];
__device__ float g_q[Nn * Dd];
__device__ float g_k[Nn * Dd];
__device__ float g_v[Nn * Dd];
__device__ float g_att[Nn * Dd];
__device__ float g_t1[Nn * DFFf];
__device__ float g_t2[Nn * Dd];
__device__ unsigned char g_e8[Nn * Nn];
__device__ float g_pool[2 * Dd];

// ---------------- embedding gather ----------------
__global__ void embed_kernel(const int* __restrict__ nt, const float* __restrict__ emb,
                             float* __restrict__ x) {
    int i = blockIdx.x;
    int d = threadIdx.x;
    x[i * Dd + d] = emb[nt[i] * Dd + d];
}

// ---------------- int32 edge matrix -> uint8 (read 32x later) ----------------
__global__ void cvt_e8_kernel(const int* __restrict__ e, unsigned char* __restrict__ o) {
    int i = blockIdx.x * blockDim.x + threadIdx.x;  // over N*N/4
    int4 v = ((const int4*)e)[i];
    uchar4 u;
    u.x = (unsigned char)v.x; u.y = (unsigned char)v.y;
    u.z = (unsigned char)v.z; u.w = (unsigned char)v.w;
    ((uchar4*)o)[i] = u;
}

// ---------------- tiled SGEMM: C[rows,M] = A[rows,Kd] @ B[Kd,M] (+bias)(+gelu) ---
// grid: (M/64, rows/64), block: 256 threads, 4x4 per thread
template <int ACT>
__global__ void __launch_bounds__(256) gemm_kernel(
    const float* __restrict__ A, const float* __restrict__ B,
    const float* __restrict__ bias, float* __restrict__ C, int Kd, int M) {
    __shared__ float AsT[16][64];
    __shared__ float Bs[16][64];
    const int tid = threadIdx.x;
    const int tx = tid & 15, ty = tid >> 4;
    const int i0 = blockIdx.y << 6, j0 = blockIdx.x << 6;

    float acc[4][4];
#pragma unroll
    for (int r = 0; r < 4; r++)
#pragma unroll
        for (int c = 0; c < 4; c++) acc[r][c] = 0.f;

    const int aRow = tid >> 2, aK4 = (tid & 3) << 2;
    const int bK = tid >> 4, bC4 = (tid & 15) << 2;

    for (int kt = 0; kt < Kd; kt += 16) {
        float4 av = *(const float4*)&A[(size_t)(i0 + aRow) * Kd + kt + aK4];
        float4 bv = *(const float4*)&B[(size_t)(kt + bK) * M + j0 + bC4];
        AsT[aK4 + 0][aRow] = av.x;
        AsT[aK4 + 1][aRow] = av.y;
        AsT[aK4 + 2][aRow] = av.z;
        AsT[aK4 + 3][aRow] = av.w;
        *(float4*)&Bs[bK][bC4] = bv;
        __syncthreads();
#pragma unroll
        for (int k = 0; k < 16; k++) {
            float4 a = *(const float4*)&AsT[k][ty << 2];
            float4 b = *(const float4*)&Bs[k][tx << 2];
            float ar[4] = {a.x, a.y, a.z, a.w};
            float br_[4] = {b.x, b.y, b.z, b.w};
#pragma unroll
            for (int r = 0; r < 4; r++)
#pragma unroll
                for (int c = 0; c < 4; c++) acc[r][c] = fmaf(ar[r], br_[c], acc[r][c]);
        }
        __syncthreads();
    }

#pragma unroll
    for (int r = 0; r < 4; r++) {
        float4 o;
        float* po = &o.x;
#pragma unroll
        for (int c = 0; c < 4; c++) {
            float v = acc[r][c];
            if (bias) v += bias[j0 + (tx << 2) + c];
            if (ACT == 1) v = 0.5f * v * (1.0f + erff(v * 0.70710678118654752f));
            po[c] = v;
        }
        *(float4*)&C[(size_t)(i0 + (ty << 2) + r) * M + j0 + (tx << 2)] = o;
    }
}

// ---------------- flash attention with edge bias ----------------
// grid: (N/64, H), block 256. Each thread: 4 rows x 2 out-cols.
__global__ void __launch_bounds__(256) attn_kernel(
    const float* __restrict__ Qg, const float* __restrict__ Kg, const float* __restrict__ Vg,
    const unsigned char* __restrict__ E8, const float* __restrict__ ebl,
    float* __restrict__ Og) {
    const int h = blockIdx.y;
    const int i0 = blockIdx.x << 6;
    const int tid = threadIdx.x;
    const int tx = tid & 15, ty = tid >> 4;

    __shared__ float QsT[DKk][64];
    __shared__ float KsT[DKk][64];
    __shared__ float Vs[64][DKk];
    __shared__ float Ps[64][65];
    __shared__ float s_eb[8];

    if (tid < NEDGEe) s_eb[tid] = ebl[tid * Hh + h];

#pragma unroll
    for (int it = 0; it < 2; it++) {
        int ff = tid + it * 256;
        int row = ff >> 3, c4 = (ff & 7) << 2;
        float4 q = *(const float4*)&Qg[(size_t)(i0 + row) * Dd + h * DKk + c4];
        QsT[c4 + 0][row] = q.x;
        QsT[c4 + 1][row] = q.y;
        QsT[c4 + 2][row] = q.z;
        QsT[c4 + 3][row] = q.w;
    }

    float m[4], l[4], o[4][2];
#pragma unroll
    for (int r = 0; r < 4; r++) {
        m[r] = -1e30f; l[r] = 0.f; o[r][0] = 0.f; o[r][1] = 0.f;
    }
    const float scale = 0.17677669529663687f;  // 1/sqrt(32)

    for (int jt = 0; jt < Nn; jt += 64) {
        __syncthreads();  // protect Ps/KsT/Vs from prev-iter reads; covers Q stores on iter 0
#pragma unroll
        for (int it = 0; it < 2; it++) {
            int ff = tid + it * 256;
            int row = ff >> 3, c4 = (ff & 7) << 2;
            float4 kv = *(const float4*)&Kg[(size_t)(jt + row) * Dd + h * DKk + c4];
            KsT[c4 + 0][row] = kv.x;
            KsT[c4 + 1][row] = kv.y;
            KsT[c4 + 2][row] = kv.z;
            KsT[c4 + 3][row] = kv.w;
            float4 vv = *(const float4*)&Vg[(size_t)(jt + row) * Dd + h * DKk + c4];
            *(float4*)&Vs[row][c4] = vv;
        }
        __syncthreads();

        float s[4][4];
#pragma unroll
        for (int r = 0; r < 4; r++)
#pragma unroll
            for (int c = 0; c < 4; c++) s[r][c] = 0.f;

#pragma unroll
        for (int k = 0; k < DKk; k++) {
            float4 a = *(const float4*)&QsT[k][ty << 2];
            float4 b = *(const float4*)&KsT[k][tx << 2];
            float ar[4] = {a.x, a.y, a.z, a.w};
            float br_[4] = {b.x, b.y, b.z, b.w};
#pragma unroll
            for (int r = 0; r < 4; r++)
#pragma unroll
                for (int c = 0; c < 4; c++) s[r][c] = fmaf(ar[r], br_[c], s[r][c]);
        }

        // scale + edge bias (uint8 indices, 4 at a time)
#pragma unroll
        for (int r = 0; r < 4; r++) {
            unsigned int e4 =
                *(const unsigned int*)&E8[(size_t)(i0 + (ty << 2) + r) * Nn + jt + (tx << 2)];
            s[r][0] = fmaf(s[r][0], scale, s_eb[e4 & 0xffu]);
            s[r][1] = fmaf(s[r][1], scale, s_eb[(e4 >> 8) & 0xffu]);
            s[r][2] = fmaf(s[r][2], scale, s_eb[(e4 >> 16) & 0xffu]);
            s[r][3] = fmaf(s[r][3], scale, s_eb[(e4 >> 24) & 0xffu]);
        }

        // online softmax (row owned by 16 tx-lanes; tx = low 4 bits of lane id)
#pragma unroll
        for (int r = 0; r < 4; r++) {
            float rm = fmaxf(fmaxf(s[r][0], s[r][1]), fmaxf(s[r][2], s[r][3]));
#pragma unroll
            for (int off = 1; off < 16; off <<= 1)
                rm = fmaxf(rm, __shfl_xor_sync(0xffffffffu, rm, off));
            float mnew = fmaxf(m[r], rm);
            float alpha = __expf(m[r] - mnew);
            m[r] = mnew;
            o[r][0] *= alpha;
            o[r][1] *= alpha;
            float ps = 0.f;
#pragma unroll
            for (int c = 0; c < 4; c++) {
                float p = __expf(s[r][c] - mnew);
                ps += p;
                Ps[(ty << 2) + r][(tx << 2) + c] = p;
            }
#pragma unroll
            for (int off = 1; off < 16; off <<= 1)
                ps += __shfl_xor_sync(0xffffffffu, ps, off);
            l[r] = l[r] * alpha + ps;
        }
        __syncthreads();

        // O += P @ V
#pragma unroll 4
        for (int j = 0; j < 64; j++) {
            float2 v = *(const float2*)&Vs[j][tx << 1];
#pragma unroll
            for (int r = 0; r < 4; r++) {
                float p = Ps[(ty << 2) + r][j];
                o[r][0] = fmaf(p, v.x, o[r][0]);
                o[r][1] = fmaf(p, v.y, o[r][1]);
            }
        }
    }

#pragma unroll
    for (int r = 0; r < 4; r++) {
        float inv = 1.0f / l[r];
        float2 ov = make_float2(o[r][0] * inv, o[r][1] * inv);
        *(float2*)&Og[(size_t)(i0 + (ty << 2) + r) * Dd + h * DKk + (tx << 1)] = ov;
    }
}

// ---------------- residual add + LayerNorm (in-place on x) ----------------
__global__ void addln_kernel(float* __restrict__ x, const float* __restrict__ h,
                             const float* __restrict__ g, const float* __restrict__ b) {
    int i = blockIdx.x, d = threadIdx.x;
    __shared__ float red[256];
    float v = x[i * Dd + d] + h[i * Dd + d];
    red[d] = v;
    __syncthreads();
    for (int s = 128; s > 0; s >>= 1) {
        if (d < s) red[d] += red[d + s];
        __syncthreads();
    }
    float mean = red[0] * (1.0f / Dd);
    __syncthreads();
    float dv = v - mean;
    red[d] = dv * dv;
    __syncthreads();
    for (int s = 128; s > 0; s >>= 1) {
        if (d < s) red[d] += red[d + s];
        __syncthreads();
    }
    float var = red[0] * (1.0f / Dd);
    x[i * Dd + d] = dv * rsqrtf(var + 1e-5f) * g[d] + b[d];
}

// ---------------- column-wise mean/max pooling ----------------
__global__ void pool_kernel(const float* __restrict__ x, float* __restrict__ p) {
    int j = blockIdx.x * 32 + threadIdx.x;
    int yy = threadIdx.y;
    float s = 0.f, mx = -1e30f;
    for (int i = yy; i < Nn; i += 8) {
        float v = x[(size_t)i * Dd + j];
        s += v;
        mx = fmaxf(mx, v);
    }
    __shared__ float ss[8][33], sm[8][33];
    ss[yy][threadIdx.x] = s;
    sm[yy][threadIdx.x] = mx;
    __syncthreads();
    if (yy == 0) {
        for (int k2 = 1; k2 < 8; k2++) {
            s += ss[k2][threadIdx.x];
            mx = fmaxf(mx, sm[k2][threadIdx.x]);
        }
        p[j] = s * (1.0f / Nn);
        p[Dd + j] = mx;
    }
}

// ---------------- final head: out = pooled @ Wr + br ----------------
__global__ void head_kernel(const float* __restrict__ pooled, const float* __restrict__ Wr,
                            const float* __restrict__ br, float* __restrict__ out) {
    __shared__ float sp[2 * Dd];
    int d = threadIdx.x;
    sp[d] = pooled[d];
    sp[d + Dd] = pooled[d + Dd];
    __syncthreads();
    float acc = br[d];
#pragma unroll 8
    for (int k2 = 0; k2 < 2 * Dd; k2++) acc = fmaf(sp[k2], Wr[(size_t)k2 * Dd + d], acc);
    out[d] = acc;
}

// ---------------- host launcher ----------------
extern "C" void kernel_launch(void* const* d_in, const int* in_sizes, int n_in,
                              void* d_out, int out_size) {
    const int* node_types = (const int*)d_in[0];
    const int* edge_idx = (const int*)d_in[1];
    const float* node_emb = (const float*)d_in[2];
    const float* Wq = (const float*)d_in[3];
    const float* Wk = (const float*)d_in[4];
    const float* Wv = (const float*)d_in[5];
    const float* Wo = (const float*)d_in[6];
    const float* bo = (const float*)d_in[7];
    const float* eb = (const float*)d_in[8];
    const float* W1 = (const float*)d_in[9];
    const float* b1 = (const float*)d_in[10];
    const float* W2 = (const float*)d_in[11];
    const float* b2 = (const float*)d_in[12];
    const float* ln1g = (const float*)d_in[13];
    const float* ln1b = (const float*)d_in[14];
    const float* ln2g = (const float*)d_in[15];
    const float* ln2b = (const float*)d_in[16];
    const float* Wr = (const float*)d_in[17];
    const float* brr = (const float*)d_in[18];
    float* out = (float*)d_out;

    float *x, *q, *k, *v, *att, *t1, *t2, *pool;
    unsigned char* e8;
    cudaGetSymbolAddress((void**)&x, g_x);
    cudaGetSymbolAddress((void**)&q, g_q);
    cudaGetSymbolAddress((void**)&k, g_k);
    cudaGetSymbolAddress((void**)&v, g_v);
    cudaGetSymbolAddress((void**)&att, g_att);
    cudaGetSymbolAddress((void**)&t1, g_t1);
    cudaGetSymbolAddress((void**)&t2, g_t2);
    cudaGetSymbolAddress((void**)&pool, g_pool);
    cudaGetSymbolAddress((void**)&e8, g_e8);

    embed_kernel<<<Nn, Dd>>>(node_types, node_emb, x);
    cvt_e8_kernel<<<(Nn * Nn / 4) / 256, 256>>>(edge_idx, e8);

    for (int l = 0; l < Ll; l++) {
        dim3 gProj(Dd / 64, Nn / 64);
        gemm_kernel<0><<<gProj, 256>>>(x, Wq + (size_t)l * Dd * Dd, nullptr, q, Dd, Dd);
        gemm_kernel<0><<<gProj, 256>>>(x, Wk + (size_t)l * Dd * Dd, nullptr, k, Dd, Dd);
        gemm_kernel<0><<<gProj, 256>>>(x, Wv + (size_t)l * Dd * Dd, nullptr, v, Dd, Dd);

        attn_kernel<<<dim3(Nn / 64, Hh), 256>>>(q, k, v, e8, eb + l * NEDGEe * Hh, att);

        gemm_kernel<0><<<gProj, 256>>>(att, Wo + (size_t)l * Dd * Dd, bo + l * Dd, t2, Dd, Dd);
        addln_kernel<<<Nn, Dd>>>(x, t2, ln1g + l * Dd, ln1b + l * Dd);

        gemm_kernel<1><<<dim3(DFFf / 64, Nn / 64), 256>>>(x, W1 + (size_t)l * Dd * DFFf,
                                                          b1 + l * DFFf, t1, Dd, DFFf);
        gemm_kernel<0><<<gProj, 256>>>(t1, W2 + (size_t)l * DFFf * Dd, b2 + l * Dd, t2, DFFf, Dd);
        addln_kernel<<<Nn, Dd>>>(x, t2, ln2g + l * Dd, ln2b + l * Dd);
    }

    pool_kernel<<<Dd / 32, dim3(32, 8)>>>(x, pool);
    head_kernel<<<1, Dd>>>(pool, Wr, brr, out);
}

// round 2
// speedup vs baseline: 1.1243x; 1.1243x over previous
#include <cuda_runtime.h>
#include <math.h>

#define Nn 2048
#define Dd 256
#define Hh 8
#define DKk 32
#define Ll 4
#define DFFf 1024
#define NEDGEe 5

typedef unsigned long long u64t;

// packed fp32x2 FMA (FFMA2): 2 FLOPs per fma-pipe slot
__device__ __forceinline__ u64t ffma2(u64t a, u64t b, u64t c) {
    u64t d;
    asm("fma.rn.f32x2 %0, %1, %2, %3;" : "=l"(d) : "l"(a), "l"(b), "l"(c));
    return d;
}
__device__ __forceinline__ u64t bcast2(float x) {
    u64t r;
    asm("mov.b64 %0, {%1, %1};" : "=l"(r) : "f"(x), "f"(x));
    return r;
}
union f2u { u64t u; float2 f; };

// ---------------- scratch (static device globals: no allocation) ----------------
__device__ float g_x[Nn * Dd];
__device__ float g_q[Nn * Dd];
__device__ float g_k[Nn * Dd];
__device__ float g_v[Nn * Dd];
__device__ float g_att[Nn * Dd];
__device__ float g_t1[Nn * DFFf];
__device__ float g_part[4 * Nn * Dd];
__device__ unsigned char g_e8[Nn * Nn];
__device__ float g_pool[2 * Dd];

// ---------------- embedding gather ----------------
__global__ void embed_kernel(const int* __restrict__ nt, const float* __restrict__ emb,
                             float* __restrict__ x) {
    int i = blockIdx.x;
    int d = threadIdx.x;
    x[i * Dd + d] = emb[nt[i] * Dd + d];
}

// ---------------- int32 edge matrix -> uint8 ----------------
__global__ void cvt_e8_kernel(const int* __restrict__ e, unsigned char* __restrict__ o) {
    int i = blockIdx.x * blockDim.x + threadIdx.x;
    int4 v = ((const int4*)e)[i];
    uchar4 u;
    u.x = (unsigned char)v.x; u.y = (unsigned char)v.y;
    u.z = (unsigned char)v.z; u.w = (unsigned char)v.w;
    ((uchar4*)o)[i] = u;
}

// ---------------- common GEMM body: C[64x64 tile] = A[:,kbeg:kend] @ B ----------
// block 256 threads, per-thread 4x4 via f32x2. i0/j0 from blockIdx.y/x.
template <int ACT>
__device__ __forceinline__ void gemm_body(const float* __restrict__ A,
                                          const float* __restrict__ B,
                                          const float* __restrict__ bias,
                                          float* __restrict__ C, int Kd, int M,
                                          int kbeg, int kend) {
    __shared__ float AsT[16][64];
    __shared__ float Bs[16][64];
    const int tid = threadIdx.x;
    const int tx = tid & 15, ty = tid >> 4;
    const int i0 = blockIdx.y << 6, j0 = blockIdx.x << 6;

    u64t acc[4][2];
#pragma unroll
    for (int r = 0; r < 4; r++) { acc[r][0] = 0ull; acc[r][1] = 0ull; }

    const int aRow = tid >> 2, aK4 = (tid & 3) << 2;
    const int bK = tid >> 4, bC4 = (tid & 15) << 2;

    for (int kt = kbeg; kt < kend; kt += 16) {
        float4 av = *(const float4*)&A[(size_t)(i0 + aRow) * Kd + kt + aK4];
        float4 bv = *(const float4*)&B[(size_t)(kt + bK) * M + j0 + bC4];
        AsT[aK4 + 0][aRow] = av.x;
        AsT[aK4 + 1][aRow] = av.y;
        AsT[aK4 + 2][aRow] = av.z;
        AsT[aK4 + 3][aRow] = av.w;
        *(float4*)&Bs[bK][bC4] = bv;
        __syncthreads();
#pragma unroll
        for (int k = 0; k < 16; k++) {
            float4 a = *(const float4*)&AsT[k][ty << 2];
            ulonglong2 b = *(const ulonglong2*)&Bs[k][tx << 2];
            u64t a0 = bcast2(a.x), a1 = bcast2(a.y), a2 = bcast2(a.z), a3 = bcast2(a.w);
            acc[0][0] = ffma2(a0, b.x, acc[0][0]);
            acc[0][1] = ffma2(a0, b.y, acc[0][1]);
            acc[1][0] = ffma2(a1, b.x, acc[1][0]);
            acc[1][1] = ffma2(a1, b.y, acc[1][1]);
            acc[2][0] = ffma2(a2, b.x, acc[2][0]);
            acc[2][1] = ffma2(a2, b.y, acc[2][1]);
            acc[3][0] = ffma2(a3, b.x, acc[3][0]);
            acc[3][1] = ffma2(a3, b.y, acc[3][1]);
        }
        __syncthreads();
    }

#pragma unroll
    for (int r = 0; r < 4; r++) {
        f2u c0, c1;
        c0.u = acc[r][0];
        c1.u = acc[r][1];
        float vv[4] = {c0.f.x, c0.f.y, c1.f.x, c1.f.y};
        float4 o;
        float* po = &o.x;
#pragma unroll
        for (int c = 0; c < 4; c++) {
            float v = vv[c];
            if (bias) v += bias[j0 + (tx << 2) + c];
            if (ACT == 1) v = 0.5f * v * (1.0f + erff(v * 0.70710678118654752f));
            po[c] = v;
        }
        *(float4*)&C[(size_t)(i0 + (ty << 2) + r) * M + j0 + (tx << 2)] = o;
    }
}

// general GEMM with optional K-split (grid.z): partial z writes to C + z*Nn*M
template <int ACT, int SPLIT>
__global__ void __launch_bounds__(256) gemm_kernel(const float* __restrict__ A,
                                                   const float* __restrict__ B,
                                                   const float* __restrict__ bias,
                                                   float* __restrict__ C, int Kd, int M) {
    int kslice = Kd / SPLIT;
    int kbeg = blockIdx.z * kslice;
    float* Cz = C + (size_t)blockIdx.z * Nn * M;
    gemm_body<ACT>(A, B, SPLIT == 1 ? bias : nullptr, Cz, Kd, M, kbeg, kbeg + kslice);
}

// batched QKV: grid.z in {0,1,2} selects weight + destination
__global__ void __launch_bounds__(256) gemm_qkv_kernel(
    const float* __restrict__ A, const float* __restrict__ Wq,
    const float* __restrict__ Wk, const float* __restrict__ Wv,
    float* __restrict__ q, float* __restrict__ k, float* __restrict__ v) {
    int z = blockIdx.z;
    const float* B = (z == 0) ? Wq : (z == 1) ? Wk : Wv;
    float* C = (z == 0) ? q : (z == 1) ? k : v;
    gemm_body<0>(A, B, nullptr, C, Dd, Dd, 0, Dd);
}

// ---------------- flash attention with edge bias ----------------
__global__ void __launch_bounds__(256) attn_kernel(
    const float* __restrict__ Qg, const float* __restrict__ Kg, const float* __restrict__ Vg,
    const unsigned char* __restrict__ E8, const float* __restrict__ ebl,
    float* __restrict__ Og) {
    const int h = blockIdx.y;
    const int i0 = blockIdx.x << 6;
    const int tid = threadIdx.x;
    const int tx = tid & 15, ty = tid >> 4;

    __shared__ float QsT[DKk][64];
    __shared__ float KsT[DKk][64];
    __shared__ float Vs[64][DKk];
    __shared__ float Ps[64][65];
    __shared__ float s_eb[8];

    if (tid < NEDGEe) s_eb[tid] = ebl[tid * Hh + h];

#pragma unroll
    for (int it = 0; it < 2; it++) {
        int ff = tid + it * 256;
        int row = ff >> 3, c4 = (ff & 7) << 2;
        float4 q = *(const float4*)&Qg[(size_t)(i0 + row) * Dd + h * DKk + c4];
        QsT[c4 + 0][row] = q.x;
        QsT[c4 + 1][row] = q.y;
        QsT[c4 + 2][row] = q.z;
        QsT[c4 + 3][row] = q.w;
    }

    float m[4], l[4], o[4][2];
#pragma unroll
    for (int r = 0; r < 4; r++) {
        m[r] = -1e30f; l[r] = 0.f; o[r][0] = 0.f; o[r][1] = 0.f;
    }
    const float scale = 0.17677669529663687f;  // 1/sqrt(32)

    for (int jt = 0; jt < Nn; jt += 64) {
        __syncthreads();
#pragma unroll
        for (int it = 0; it < 2; it++) {
            int ff = tid + it * 256;
            int row = ff >> 3, c4 = (ff & 7) << 2;
            float4 kv = *(const float4*)&Kg[(size_t)(jt + row) * Dd + h * DKk + c4];
            KsT[c4 + 0][row] = kv.x;
            KsT[c4 + 1][row] = kv.y;
            KsT[c4 + 2][row] = kv.z;
            KsT[c4 + 3][row] = kv.w;
            float4 vv = *(const float4*)&Vg[(size_t)(jt + row) * Dd + h * DKk + c4];
            *(float4*)&Vs[row][c4] = vv;
        }
        __syncthreads();

        // S = Q K^T via f32x2
        u64t s2[4][2];
#pragma unroll
        for (int r = 0; r < 4; r++) { s2[r][0] = 0ull; s2[r][1] = 0ull; }
#pragma unroll
        for (int k = 0; k < DKk; k++) {
            float4 a = *(const float4*)&QsT[k][ty << 2];
            ulonglong2 b = *(const ulonglong2*)&KsT[k][tx << 2];
            u64t a0 = bcast2(a.x), a1 = bcast2(a.y), a2 = bcast2(a.z), a3 = bcast2(a.w);
            s2[0][0] = ffma2(a0, b.x, s2[0][0]);
            s2[0][1] = ffma2(a0, b.y, s2[0][1]);
            s2[1][0] = ffma2(a1, b.x, s2[1][0]);
            s2[1][1] = ffma2(a1, b.y, s2[1][1]);
            s2[2][0] = ffma2(a2, b.x, s2[2][0]);
            s2[2][1] = ffma2(a2, b.y, s2[2][1]);
            s2[3][0] = ffma2(a3, b.x, s2[3][0]);
            s2[3][1] = ffma2(a3, b.y, s2[3][1]);
        }

        float s[4][4];
#pragma unroll
        for (int r = 0; r < 4; r++) {
            f2u c0, c1;
            c0.u = s2[r][0];
            c1.u = s2[r][1];
            s[r][0] = c0.f.x; s[r][1] = c0.f.y; s[r][2] = c1.f.x; s[r][3] = c1.f.y;
        }

        // scale + edge bias
#pragma unroll
        for (int r = 0; r < 4; r++) {
            unsigned int e4 =
                *(const unsigned int*)&E8[(size_t)(i0 + (ty << 2) + r) * Nn + jt + (tx << 2)];
            s[r][0] = fmaf(s[r][0], scale, s_eb[e4 & 0xffu]);
            s[r][1] = fmaf(s[r][1], scale, s_eb[(e4 >> 8) & 0xffu]);
            s[r][2] = fmaf(s[r][2], scale, s_eb[(e4 >> 16) & 0xffu]);
            s[r][3] = fmaf(s[r][3], scale, s_eb[(e4 >> 24) & 0xffu]);
        }

        // online softmax
#pragma unroll
        for (int r = 0; r < 4; r++) {
            float rm = fmaxf(fmaxf(s[r][0], s[r][1]), fmaxf(s[r][2], s[r][3]));
#pragma unroll
            for (int off = 1; off < 16; off <<= 1)
                rm = fmaxf(rm, __shfl_xor_sync(0xffffffffu, rm, off));
            float mnew = fmaxf(m[r], rm);
            float alpha = __expf(m[r] - mnew);
            m[r] = mnew;
            o[r][0] *= alpha;
            o[r][1] *= alpha;
            float ps = 0.f;
#pragma unroll
            for (int c = 0; c < 4; c++) {
                float p = __expf(s[r][c] - mnew);
                ps += p;
                Ps[(ty << 2) + r][(tx << 2) + c] = p;
            }
#pragma unroll
            for (int off = 1; off < 16; off <<= 1)
                ps += __shfl_xor_sync(0xffffffffu, ps, off);
            l[r] = l[r] * alpha + ps;
        }
        __syncthreads();

        // O += P @ V
#pragma unroll 4
        for (int j = 0; j < 64; j++) {
            float2 v = *(const float2*)&Vs[j][tx << 1];
#pragma unroll
            for (int r = 0; r < 4; r++) {
                float p = Ps[(ty << 2) + r][j];
                o[r][0] = fmaf(p, v.x, o[r][0]);
                o[r][1] = fmaf(p, v.y, o[r][1]);
            }
        }
    }

#pragma unroll
    for (int r = 0; r < 4; r++) {
        float inv = 1.0f / l[r];
        float2 ov = make_float2(o[r][0] * inv, o[r][1] * inv);
        *(float2*)&Og[(size_t)(i0 + (ty << 2) + r) * Dd + h * DKk + (tx << 1)] = ov;
    }
}

// ---------------- partial-sum reduce + bias + residual + LayerNorm ----------------
template <int S>
__global__ void addln_red_kernel(float* __restrict__ x, const float* __restrict__ part,
                                 const float* __restrict__ bias, const float* __restrict__ g,
                                 const float* __restrict__ b) {
    int i = blockIdx.x, d = threadIdx.x;
    __shared__ float red[256];
    float v = x[i * Dd + d] + bias[d];
#pragma unroll
    for (int s = 0; s < S; s++) v += part[(size_t)s * Nn * Dd + (size_t)i * Dd + d];
    red[d] = v;
    __syncthreads();
    for (int s = 128; s > 0; s >>= 1) {
        if (d < s) red[d] += red[d + s];
        __syncthreads();
    }
    float mean = red[0] * (1.0f / Dd);
    __syncthreads();
    float dv = v - mean;
    red[d] = dv * dv;
    __syncthreads();
    for (int s = 128; s > 0; s >>= 1) {
        if (d < s) red[d] += red[d + s];
        __syncthreads();
    }
    float var = red[0] * (1.0f / Dd);
    x[i * Dd + d] = dv * rsqrtf(var + 1e-5f) * g[d] + b[d];
}

// ---------------- column-wise mean/max pooling ----------------
__global__ void pool_kernel(const float* __restrict__ x, float* __restrict__ p) {
    int j = blockIdx.x * 32 + threadIdx.x;
    int yy = threadIdx.y;
    float s = 0.f, mx = -1e30f;
    for (int i = yy; i < Nn; i += 8) {
        float v = x[(size_t)i * Dd + j];
        s += v;
        mx = fmaxf(mx, v);
    }
    __shared__ float ss[8][33], sm[8][33];
    ss[yy][threadIdx.x] = s;
    sm[yy][threadIdx.x] = mx;
    __syncthreads();
    if (yy == 0) {
        for (int k2 = 1; k2 < 8; k2++) {
            s += ss[k2][threadIdx.x];
            mx = fmaxf(mx, sm[k2][threadIdx.x]);
        }
        p[j] = s * (1.0f / Nn);
        p[Dd + j] = mx;
    }
}

// ---------------- final head ----------------
__global__ void head_kernel(const float* __restrict__ pooled, const float* __restrict__ Wr,
                            const float* __restrict__ br, float* __restrict__ out) {
    __shared__ float sp[2 * Dd];
    int d = threadIdx.x;
    sp[d] = pooled[d];
    sp[d + Dd] = pooled[d + Dd];
    __syncthreads();
    float acc = br[d];
#pragma unroll 8
    for (int k2 = 0; k2 < 2 * Dd; k2++) acc = fmaf(sp[k2], Wr[(size_t)k2 * Dd + d], acc);
    out[d] = acc;
}

// ---------------- host launcher ----------------
extern "C" void kernel_launch(void* const* d_in, const int* in_sizes, int n_in,
                              void* d_out, int out_size) {
    const int* node_types = (const int*)d_in[0];
    const int* edge_idx = (const int*)d_in[1];
    const float* node_emb = (const float*)d_in[2];
    const float* Wq = (const float*)d_in[3];
    const float* Wk = (const float*)d_in[4];
    const float* Wv = (const float*)d_in[5];
    const float* Wo = (const float*)d_in[6];
    const float* bo = (const float*)d_in[7];
    const float* eb = (const float*)d_in[8];
    const float* W1 = (const float*)d_in[9];
    const float* b1 = (const float*)d_in[10];
    const float* W2 = (const float*)d_in[11];
    const float* b2 = (const float*)d_in[12];
    const float* ln1g = (const float*)d_in[13];
    const float* ln1b = (const float*)d_in[14];
    const float* ln2g = (const float*)d_in[15];
    const float* ln2b = (const float*)d_in[16];
    const float* Wr = (const float*)d_in[17];
    const float* brr = (const float*)d_in[18];
    float* out = (float*)d_out;

    float *x, *q, *k, *v, *att, *t1, *part, *pool;
    unsigned char* e8;
    cudaGetSymbolAddress((void**)&x, g_x);
    cudaGetSymbolAddress((void**)&q, g_q);
    cudaGetSymbolAddress((void**)&k, g_k);
    cudaGetSymbolAddress((void**)&v, g_v);
    cudaGetSymbolAddress((void**)&att, g_att);
    cudaGetSymbolAddress((void**)&t1, g_t1);
    cudaGetSymbolAddress((void**)&part, g_part);
    cudaGetSymbolAddress((void**)&pool, g_pool);
    cudaGetSymbolAddress((void**)&e8, g_e8);

    embed_kernel<<<Nn, Dd>>>(node_types, node_emb, x);
    cvt_e8_kernel<<<(Nn * Nn / 4) / 256, 256>>>(edge_idx, e8);

    for (int l = 0; l < Ll; l++) {
        gemm_qkv_kernel<<<dim3(4, 32, 3), 256>>>(x, Wq + (size_t)l * Dd * Dd,
                                                 Wk + (size_t)l * Dd * Dd,
                                                 Wv + (size_t)l * Dd * Dd, q, k, v);

        attn_kernel<<<dim3(Nn / 64, Hh), 256>>>(q, k, v, e8, eb + l * NEDGEe * Hh, att);

        gemm_kernel<0, 2><<<dim3(4, 32, 2), 256>>>(att, Wo + (size_t)l * Dd * Dd, nullptr,
                                                   part, Dd, Dd);
        addln_red_kernel<2><<<Nn, Dd>>>(x, part, bo + l * Dd, ln1g + l * Dd, ln1b + l * Dd);

        gemm_kernel<1, 1><<<dim3(16, 32, 1), 256>>>(x, W1 + (size_t)l * Dd * DFFf,
                                                    b1 + l * DFFf, t1, Dd, DFFf);
        gemm_kernel<0, 4><<<dim3(4, 32, 4), 256>>>(t1, W2 + (size_t)l * DFFf * Dd, nullptr,
                                                   part, DFFf, Dd);
        addln_red_kernel<4><<<Nn, Dd>>>(x, part, b2 + l * Dd, ln2g + l * Dd, ln2b + l * Dd);
    }

    pool_kernel<<<Dd / 32, dim3(32, 8)>>>(x, pool);
    head_kernel<<<1, Dd>>>(pool, Wr, brr, out);
}